// round 10
// baseline (speedup 1.0000x reference)
#include <cuda_runtime.h>
#include <cuda_fp16.h>
#include <math.h>
#include <stdint.h>

#define N_NODES 16384
#define F_DIM   256
#define H_DIM   512
#define K_TOT   768          // 256 (x) + 512 (pe)
#define NPG     64
#define NGRAPH  256
#define MAXDEG  512

// ---------------- static device scratch ----------------
__device__ __align__(16) __half g_A[N_NODES * K_TOT];   // [x | PE] fp16
__device__ __align__(16) __half g_B[H_DIM * K_TOT];     // B^T: [n][k] fp16
__device__ float g_T2[(MAXDEG + 1) * H_DIM];
__device__ float g_T4[(NPG + 1) * H_DIM];
__device__ float g_bconst[H_DIM];
__device__ unsigned long long g_adj[N_NODES];
__device__ int g_deg[N_NODES];
__device__ __align__(16) float g_scg[NGRAPH * H_DIM];   // sin/cos(64g * inv_k) pairs
__device__ __align__(16) float g_scr[NPG * H_DIM];      // sin/cos(r * inv_k) pairs

// ---------------- helpers ----------------
__device__ __forceinline__ uint32_t smem_u32(const void* p) {
    uint32_t a;
    asm("{ .reg .u64 t; cvta.to.shared.u64 t, %1; cvt.u32.u64 %0, t; }" : "=r"(a) : "l"(p));
    return a;
}
__device__ __forceinline__ void cpasync16(uint32_t dst, const void* src) {
    asm volatile("cp.async.cg.shared.global [%0], [%1], 16;" :: "r"(dst), "l"(src) : "memory");
}
#define CP_COMMIT() asm volatile("cp.async.commit_group;" ::: "memory")
#define CP_WAIT2()  asm volatile("cp.async.wait_group 2;" ::: "memory")

#define LDSM4(r, addr) \
    asm volatile("ldmatrix.sync.aligned.m8n8.x4.shared.b16 {%0,%1,%2,%3}, [%4];" \
        : "=r"((r)[0]), "=r"((r)[1]), "=r"((r)[2]), "=r"((r)[3]) : "r"(addr))

#define MMA16816(d, a, b) \
    asm volatile("mma.sync.aligned.m16n8k16.row.col.f32.f16.f16.f32 " \
        "{%0,%1,%2,%3}, {%4,%5,%6,%7}, {%8,%9}, {%0,%1,%2,%3};" \
        : "+f"((d)[0]), "+f"((d)[1]), "+f"((d)[2]), "+f"((d)[3]) \
        : "r"((a)[0]), "r"((a)[1]), "r"((a)[2]), "r"((a)[3]), "r"((b)[0]), "r"((b)[1]))

// ---------------- accurate PE angle (invdiv computed inline per thread) ----------------
__device__ __forceinline__ void invdiv_k(int k, float& hi, float& lo) {
    double v = exp(-(double)k * (9.210340371976184 / 256.0));
    hi = (float)v;
    lo = (float)(v - (double)hi);
}

__device__ __forceinline__ void pe_sincos_hl(float pos, float hi, float lo, float* s, float* c) {
    float p  = pos * hi;
    float e  = fmaf(pos, hi, -p);
    float al = fmaf(pos, lo, e);
    const float I2PI = 0.15915494309189535f;
    const float P2H  = 6.28318548202514648f;
    const float P2L  = -1.7484855e-7f;
    float q = rintf(p * I2PI);
    float r = fmaf(-q, P2H, p);
    r = fmaf(-q, P2L, r);
    r += al;
    sincosf(r, s, c);
}

// ---------------- prep0: clear deg/adj + sc tables (fast, unblocks everything) ----------------
// blocks: [0,64) clear, [64,384) sc
__global__ void k_prep0() {
    int b = blockIdx.x, t = threadIdx.x;
    if (b < 64) {
        int i = b * 256 + t;
        g_deg[i] = 0;
        g_adj[i] = 0ull;
        return;
    }
    int bb = b - 64;
    float hi, lo;
    invdiv_k(t, hi, lo);
    float s, c;
    if (bb < NGRAPH) {
        pe_sincos_hl((float)(64 * bb), hi, lo, &s, &c);
        g_scg[bb * H_DIM + 2 * t] = s; g_scg[bb * H_DIM + 2 * t + 1] = c;
    } else {
        int r = bb - NGRAPH;
        pe_sincos_hl((float)r, hi, lo, &s, &c);
        g_scr[r * H_DIM + 2 * t] = s; g_scr[r * H_DIM + 2 * t + 1] = c;
    }
}

// ---------------- fold (8 rows/block) + w3t ----------------
// blocks: [0,32) Wc (256 rows), [32,97) T2 (513 rows), [97,106) T4 (65 rows),
//         106 bconst, [107,171) w3t
__global__ void k_fold(const float* __restrict__ Wf, const float* __restrict__ Wout,
                       const float* __restrict__ bf, const float* __restrict__ bo) {
    int b = blockIdx.x, t = threadIdx.x;

    if (b >= 107) {             // ---- w3t ----
        __shared__ float sm[64][65];
        int idx = b - 107;
        int bx = idx & 7, by = idx >> 3;
        int lr = t >> 6, lc = t & 63;
        #pragma unroll 4
        for (int j = 0; j < 16; j++) {
            int r = lr * 16 + j;
            sm[r][lc] = Wout[(size_t)(1024 + by * 64 + r) * H_DIM + bx * 64 + lc];
        }
        __syncthreads();
        #pragma unroll 4
        for (int j = 0; j < 16; j++) {
            int nl = lr * 16 + j;
            float v = sm[lc][nl];
            int n = bx * 64 + nl;
            int k = F_DIM + by * 64 + lc;
            g_B[(size_t)n * K_TOT + k] = __float2half(v);
        }
        return;
    }

    // ---- fold: 8 rows per block ----
    __shared__ float a_sh[8][H_DIM];
    int kind, row0, nrows;
    const float* B;
    if (b < 32)       { kind = 0; row0 = b * 8;         nrows = 256; B = Wout; }
    else if (b < 97)  { kind = 1; row0 = (b - 32) * 8;  nrows = 513; B = Wout + 512 * H_DIM; }
    else if (b < 106) { kind = 2; row0 = (b - 97) * 8;  nrows = 65;  B = Wout + 1536 * H_DIM; }
    else              { kind = 3; row0 = 0;             nrows = 1;   B = Wout; }

    if (kind == 0) {
        #pragma unroll
        for (int r = 0; r < 8; r++) {
            a_sh[r][t]       = Wf[(row0 + r) * H_DIM + t];
            a_sh[r][t + 256] = Wf[(row0 + r) * H_DIM + t + 256];
        }
    } else if (kind == 3) {
        a_sh[0][t] = bf[t]; a_sh[0][t + 256] = bf[t + 256];
        #pragma unroll
        for (int r = 1; r < 8; r++) { a_sh[r][t] = 0.f; a_sh[r][t + 256] = 0.f; }
    } else {
        float hi, lo;
        invdiv_k(t, hi, lo);
        #pragma unroll
        for (int r = 0; r < 8; r++) {
            float s, c;
            float pos = (float)(row0 + r < nrows ? row0 + r : 0);
            pe_sincos_hl(pos, hi, lo, &s, &c);
            a_sh[r][2 * t] = s; a_sh[r][2 * t + 1] = c;
        }
    }
    __syncthreads();

    float acc[8][2];
    #pragma unroll
    for (int r = 0; r < 8; r++) { acc[r][0] = 0.f; acc[r][1] = 0.f; }

    const float2* Bp = ((const float2*)B) + t;
    #pragma unroll 8
    for (int h = 0; h < H_DIM; h++) {
        float2 w = Bp[(size_t)h * 256];
        #pragma unroll
        for (int r = 0; r < 8; r++) {
            acc[r][0] = fmaf(a_sh[r][h], w.x, acc[r][0]);
            acc[r][1] = fmaf(a_sh[r][h], w.y, acc[r][1]);
        }
    }

    int c0 = 2 * t;
    if (kind == 0) {
        #pragma unroll
        for (int r = 0; r < 8; r++) {
            g_B[(size_t)c0 * K_TOT + row0 + r]       = __float2half(acc[r][0]);
            g_B[(size_t)(c0 + 1) * K_TOT + row0 + r] = __float2half(acc[r][1]);
        }
    } else if (kind == 1) {
        #pragma unroll
        for (int r = 0; r < 8; r++) {
            if (row0 + r < 513) {
                g_T2[(size_t)(row0 + r) * H_DIM + c0]     = acc[r][0];
                g_T2[(size_t)(row0 + r) * H_DIM + c0 + 1] = acc[r][1];
            }
        }
    } else if (kind == 2) {
        #pragma unroll
        for (int r = 0; r < 8; r++) {
            if (row0 + r < 65) {
                g_T4[(size_t)(row0 + r) * H_DIM + c0]     = acc[r][0];
                g_T4[(size_t)(row0 + r) * H_DIM + c0 + 1] = acc[r][1];
            }
        }
    } else {
        g_bconst[c0]     = acc[0][0] + bo[c0];
        g_bconst[c0 + 1] = acc[0][1] + bo[c0 + 1];
    }
}

// ---------------- edges ----------------
__global__ void k_edges(const int* __restrict__ ei, int E) {
    int e = blockIdx.x * blockDim.x + threadIdx.x;
    if (e >= E) return;
    int u = ei[e], v = ei[E + e];
    atomicAdd(&g_deg[u], 1);
    atomicAdd(&g_deg[v], 1);
    atomicOr(&g_adj[u], 1ull << (v & 63));
    atomicOr(&g_adj[v], 1ull << (u & 63));
}

// ---------------- A plane: [x | PE(node idx)] -> fp16 (vectorized) ----------------
__global__ void k_aplanes(const float* __restrict__ x) {
    int i = blockIdx.x, t = threadIdx.x;
    int g = i >> 6, r = i & 63;
    float2 xv = *(const float2*)(x + (size_t)i * F_DIM + 2 * t);
    *(__half2*)(g_A + (size_t)i * K_TOT + 2 * t) = __floats2half2_rn(xv.x, xv.y);
    float4 sg = *(const float4*)(g_scg + g * H_DIM + 4 * t);
    float4 sr = *(const float4*)(g_scr + r * H_DIM + 4 * t);
    float s0 = sg.x * sr.y + sg.y * sr.x;
    float c0 = sg.y * sr.y - sg.x * sr.x;
    float s1 = sg.z * sr.w + sg.w * sr.z;
    float c1 = sg.w * sr.w - sg.z * sr.z;
    __half2 p0 = __floats2half2_rn(s0, c0);
    __half2 p1 = __floats2half2_rn(s1, c1);
    uint2 pk = make_uint2(*(uint32_t*)&p0, *(uint32_t*)&p1);
    *(uint2*)(g_A + (size_t)i * K_TOT + F_DIM + 4 * t) = pk;
}

// ---------------- HMMA GEMM + inline BFS + fused additive epilogue ----------------
// CTA tile 128x128, K-chunk 32, 8 warps (2m x 4n), warp tile 64x32.
// smem: per stage 2 planes (A, B) of 128 rows x 80B stride; 4 stages = 80KB (occ 2).
#define ROWB        80
#define PLANE_STR   (128 * ROWB)         // 10240
#define STAGE_STR   (2 * PLANE_STR)      // 20480
#define NSTAGE      4
#define GEMM_SMEM   (NSTAGE * STAGE_STR) // 81920
#define NCHUNK      24
#define MAXNNZ      40

struct EpiSmem {
    unsigned long long adj[128];
    float   bc[128];
    int     dg[128];
    int     nz[128];
    unsigned char v[128][MAXNNZ];
    unsigned char ct[128][MAXNNZ];
};

__global__ void __launch_bounds__(256, 2) k_gemm(float* __restrict__ out) {
    extern __shared__ char dsm[];
    uint32_t smem = smem_u32(dsm);

    int tid  = threadIdx.x;
    int lane = tid & 31;
    int wid  = tid >> 5;
    int wm   = wid & 1;
    int wn   = wid >> 1;
    int bn = blockIdx.x, bm = blockIdx.y;

    int lrow  = tid >> 1;
    int lhalf = tid & 1;
    const char* srcA = (const char*)(g_A + (size_t)(bm * 128 + lrow) * K_TOT) + lhalf * 32;
    const char* srcB = (const char*)(g_B + (size_t)(bn * 128 + lrow) * K_TOT) + lhalf * 32;
    uint32_t sdst = smem + (uint32_t)lrow * ROWB + (uint32_t)lhalf * 32;

    int q  = lane >> 3, rl = lane & 7;
    uint32_t aoff = (uint32_t)((wm * 64 + 8 * (q & 1) + rl) * ROWB + (8 * (q >> 1)) * 2);
    uint32_t boff = (uint32_t)((wn * 32 + 8 * (q >> 1) + rl) * ROWB + (8 * (q & 1)) * 2);

    float acc[4][4][4];
    #pragma unroll
    for (int a = 0; a < 4; a++)
        #pragma unroll
        for (int b = 0; b < 4; b++)
            #pragma unroll
            for (int e = 0; e < 4; e++) acc[a][b][e] = 0.f;

    // prologue: chunks 0,1,2 into stages 0,1,2
    #pragma unroll
    for (int s = 0; s < 3; s++) {
        uint32_t d = sdst + (uint32_t)s * STAGE_STR;
        cpasync16(d + 0 * PLANE_STR, srcA + s * 64);  cpasync16(d + 0 * PLANE_STR + 16, srcA + s * 64 + 16);
        cpasync16(d + 1 * PLANE_STR, srcB + s * 64);  cpasync16(d + 1 * PLANE_STR + 16, srcB + s * 64 + 16);
        CP_COMMIT();
    }

    for (int c = 0; c < NCHUNK; c++) {
        CP_WAIT2();
        __syncthreads();
        if (c + 3 < NCHUNK) {
            uint32_t d = sdst + (uint32_t)((c + 3) & 3) * STAGE_STR;
            const char* oA = srcA + (c + 3) * 64;
            const char* oB = srcB + (c + 3) * 64;
            cpasync16(d + 0 * PLANE_STR, oA);  cpasync16(d + 0 * PLANE_STR + 16, oA + 16);
            cpasync16(d + 1 * PLANE_STR, oB);  cpasync16(d + 1 * PLANE_STR + 16, oB + 16);
        }
        CP_COMMIT();

        uint32_t sA = smem + (uint32_t)(c & 3) * STAGE_STR;
        uint32_t sB = sA + PLANE_STR;

        #pragma unroll
        for (int kk = 0; kk < 2; kk++) {
            uint32_t ah[4][4];
            #pragma unroll
            for (int mf = 0; mf < 4; mf++) {
                uint32_t ad = sA + aoff + (uint32_t)mf * (16 * ROWB) + (uint32_t)kk * 32;
                LDSM4(ah[mf], ad);
            }
            uint32_t bh[2][4];
            #pragma unroll
            for (int nf2 = 0; nf2 < 2; nf2++) {
                uint32_t bd = sB + boff + (uint32_t)nf2 * (16 * ROWB) + (uint32_t)kk * 32;
                LDSM4(bh[nf2], bd);
            }
            #pragma unroll
            for (int mf = 0; mf < 4; mf++) {
                #pragma unroll
                for (int nf = 0; nf < 4; nf++) {
                    int nf2 = nf >> 1, nh = nf & 1;
                    MMA16816(acc[mf][nf], ah[mf], &bh[nf2][nh * 2]);
                }
            }
        }
    }

    // ---- inline BFS + fused additive epilogue ----
    __syncthreads();   // mainloop smem reads done; reuse dsm
    EpiSmem* es = (EpiSmem*)dsm;
    if (tid < 128) {
        int i = bm * 128 + tid;
        es->adj[tid] = g_adj[i];
        int d = g_deg[i]; if (d > MAXDEG) d = MAXDEG;
        es->dg[tid] = d;
    } else if (tid < 256) {
        int t = tid - 128;
        es->bc[t] = g_bconst[bn * 128 + t];
    }
    __syncthreads();

    if (tid < 128) {
        int base = tid & 64;            // graph-local adjacency block
        int s = tid & 63;
        unsigned long long reach = 1ull << s;
        unsigned long long frontier = reach;
        int m = 0;
        es->v[tid][0] = 0; es->ct[tid][0] = 1; m = 1;
        int maxfin = 0;
        for (int k = 1; k < NPG; k++) {
            unsigned long long nr = 0, f = frontier;
            while (f) {
                int j = __ffsll((long long)f) - 1;
                f &= f - 1;
                nr |= es->adj[base + j];
            }
            unsigned long long nxt = nr & ~reach;
            if (!nxt) break;
            es->v[tid][m] = (unsigned char)k;
            es->ct[tid][m] = (unsigned char)__popcll(nxt);
            m++;
            maxfin = k;
            reach |= nxt;
            frontier = nxt;
        }
        int rem = NPG - __popcll(reach);
        if (rem > 0 && m < MAXNNZ) {
            es->v[tid][m] = (unsigned char)(maxfin + 1);
            es->ct[tid][m] = (unsigned char)rem;
            m++;
        }
        es->nz[tid] = m;
    }
    __syncthreads();

    int r0l = wm * 64 + (lane >> 2);
    int c0l = wn * 32 + 2 * (lane & 3);
    #pragma unroll
    for (int mf = 0; mf < 4; mf++) {
        #pragma unroll
        for (int hh = 0; hh < 2; hh++) {
            int lr = r0l + mf * 16 + hh * 8;
            int d = es->dg[lr], m = es->nz[lr];
            const float* T2r = g_T2 + (size_t)d * H_DIM + bn * 128;
            size_t orow = (size_t)(bm * 128 + lr) * H_DIM + bn * 128;
            #pragma unroll
            for (int nf = 0; nf < 4; nf++) {
                int cl = c0l + nf * 8;
                float ax = T2r[cl]     + es->bc[cl];
                float ay = T2r[cl + 1] + es->bc[cl + 1];
                for (int j = 0; j < m; j++) {
                    float w = (float)es->ct[lr][j] * (1.0f / 64.0f);
                    const float* t4 = g_T4 + (size_t)es->v[lr][j] * H_DIM + bn * 128 + cl;
                    ax = fmaf(w, t4[0], ax);
                    ay = fmaf(w, t4[1], ay);
                }
                float2 o;
                o.x = acc[mf][nf][hh * 2 + 0] + ax;
                o.y = acc[mf][nf][hh * 2 + 1] + ay;
                *(float2*)&out[orow + cl] = o;
            }
        }
    }
}

// ---------------- launch: prep0 -> {edges | aplanes | fold} -> gemm ----------------
static cudaStream_t g_s1, g_s2;
static cudaEvent_t g_evP, g_evE, g_evA;
static int g_ready = 0;

extern "C" void kernel_launch(void* const* d_in, const int* in_sizes, int n_in,
                              void* d_out, int out_size) {
    const float* x    = (const float*)d_in[0];
    const float* Wf   = (const float*)d_in[1];
    const float* bf   = (const float*)d_in[2];
    const float* Wout = (const float*)d_in[3];
    const float* bo   = (const float*)d_in[4];
    const int*   ei   = (const int*)d_in[5];
    int E = in_sizes[5] / 2;
    float* out = (float*)d_out;

    if (!g_ready) {
        cudaStreamCreateWithFlags(&g_s1, cudaStreamNonBlocking);
        cudaStreamCreateWithFlags(&g_s2, cudaStreamNonBlocking);
        cudaEventCreateWithFlags(&g_evP, cudaEventDisableTiming);
        cudaEventCreateWithFlags(&g_evE, cudaEventDisableTiming);
        cudaEventCreateWithFlags(&g_evA, cudaEventDisableTiming);
        cudaFuncSetAttribute(k_gemm, cudaFuncAttributeMaxDynamicSharedMemorySize, GEMM_SMEM);
        g_ready = 1;
    }

    // launch 1: clear + sc tables (fast)
    k_prep0<<<384, 256>>>();
    cudaEventRecord(g_evP, 0);

    // branch: edges (needs clear)
    cudaStreamWaitEvent(g_s1, g_evP, 0);
    k_edges<<<(E + 255) / 256, 256, 0, g_s1>>>(ei, E);
    cudaEventRecord(g_evE, g_s1);

    // branch: A planes (needs sc tables)
    cudaStreamWaitEvent(g_s2, g_evP, 0);
    k_aplanes<<<N_NODES, 128, 0, g_s2>>>(x);
    cudaEventRecord(g_evA, g_s2);

    // main: fold + w3t (needs nothing from prep0)
    k_fold<<<171, 256>>>(Wf, Wout, bf, bo);

    // join + GEMM
    cudaStreamWaitEvent(0, g_evE, 0);
    cudaStreamWaitEvent(0, g_evA, 0);
    k_gemm<<<dim3(4, 128), 256, GEMM_SMEM>>>(out);
}

// round 11
// speedup vs baseline: 1.0668x; 1.0668x over previous
#include <cuda_runtime.h>
#include <cuda_fp16.h>
#include <math.h>
#include <stdint.h>

#define N_NODES 16384
#define F_DIM   256
#define H_DIM   512
#define K_TOT   768          // 256 (x) + 512 (pe)
#define NPG     64
#define NGRAPH  256
#define MAXDEG  512

// ---------------- static device scratch ----------------
__device__ __align__(16) __half g_A[N_NODES * K_TOT];   // [x | PE] fp16
__device__ __align__(16) __half g_B[H_DIM * K_TOT];     // B^T: [n][k] fp16
__device__ float g_T2[(MAXDEG + 1) * H_DIM];
__device__ float g_T4[(NPG + 1) * H_DIM];
__device__ float g_bconst[H_DIM];
__device__ unsigned long long g_adj[N_NODES];
__device__ int g_deg[N_NODES];
__device__ __align__(16) float g_scg[NGRAPH * H_DIM];   // sin/cos(64g * inv_k) pairs
__device__ __align__(16) float g_scr[NPG * H_DIM];      // sin/cos(r * inv_k) pairs

// ---------------- helpers ----------------
__device__ __forceinline__ uint32_t smem_u32(const void* p) {
    uint32_t a;
    asm("{ .reg .u64 t; cvta.to.shared.u64 t, %1; cvt.u32.u64 %0, t; }" : "=r"(a) : "l"(p));
    return a;
}
__device__ __forceinline__ void cpasync16(uint32_t dst, const void* src) {
    asm volatile("cp.async.cg.shared.global [%0], [%1], 16;" :: "r"(dst), "l"(src) : "memory");
}
#define CP_COMMIT() asm volatile("cp.async.commit_group;" ::: "memory")
#define CP_WAIT2()  asm volatile("cp.async.wait_group 2;" ::: "memory")

#define LDSM4(r, addr) \
    asm volatile("ldmatrix.sync.aligned.m8n8.x4.shared.b16 {%0,%1,%2,%3}, [%4];" \
        : "=r"((r)[0]), "=r"((r)[1]), "=r"((r)[2]), "=r"((r)[3]) : "r"(addr))

#define MMA16816(d, a, b) \
    asm volatile("mma.sync.aligned.m16n8k16.row.col.f32.f16.f16.f32 " \
        "{%0,%1,%2,%3}, {%4,%5,%6,%7}, {%8,%9}, {%0,%1,%2,%3};" \
        : "+f"((d)[0]), "+f"((d)[1]), "+f"((d)[2]), "+f"((d)[3]) \
        : "r"((a)[0]), "r"((a)[1]), "r"((a)[2]), "r"((a)[3]), "r"((b)[0]), "r"((b)[1]))

// ---------------- accurate PE angle (invdiv computed inline per thread) ----------------
__device__ __forceinline__ void invdiv_k(int k, float& hi, float& lo) {
    double v = exp(-(double)k * (9.210340371976184 / 256.0));
    hi = (float)v;
    lo = (float)(v - (double)hi);
}

__device__ __forceinline__ void pe_sincos_hl(float pos, float hi, float lo, float* s, float* c) {
    float p  = pos * hi;
    float e  = fmaf(pos, hi, -p);
    float al = fmaf(pos, lo, e);
    const float I2PI = 0.15915494309189535f;
    const float P2H  = 6.28318548202514648f;
    const float P2L  = -1.7484855e-7f;
    float q = rintf(p * I2PI);
    float r = fmaf(-q, P2H, p);
    r = fmaf(-q, P2L, r);
    r += al;
    sincosf(r, s, c);
}

// ---------------- prep0: clear deg/adj + sc tables ----------------
// blocks: [0,64) clear, [64,384) sc
__global__ void k_prep0() {
    int b = blockIdx.x, t = threadIdx.x;
    if (b < 64) {
        int i = b * 256 + t;
        g_deg[i] = 0;
        g_adj[i] = 0ull;
        return;
    }
    int bb = b - 64;
    float hi, lo;
    invdiv_k(t, hi, lo);
    float s, c;
    if (bb < NGRAPH) {
        pe_sincos_hl((float)(64 * bb), hi, lo, &s, &c);
        g_scg[bb * H_DIM + 2 * t] = s; g_scg[bb * H_DIM + 2 * t + 1] = c;
    } else {
        int r = bb - NGRAPH;
        pe_sincos_hl((float)r, hi, lo, &s, &c);
        g_scr[r * H_DIM + 2 * t] = s; g_scr[r * H_DIM + 2 * t + 1] = c;
    }
}

// ---------------- fold v3: (8-row group) x (256-col half) blocks + w3t ----------------
// groups: [0,32) Wc (256 rows), [32,97) T2 (513), [97,106) T4 (65), 106 bconst.
// blocks [0,214): fold, grp = b>>1, colhalf = b&1.  blocks [214,278): w3t.
__global__ void k_fold(const float* __restrict__ Wf, const float* __restrict__ Wout,
                       const float* __restrict__ bf, const float* __restrict__ bo) {
    int b = blockIdx.x, t = threadIdx.x;

    if (b >= 214) {             // ---- w3t ----
        __shared__ float sm[64][65];
        int idx = b - 214;
        int bx = idx & 7, by = idx >> 3;
        int lr = t >> 6, lc = t & 63;
        #pragma unroll 4
        for (int j = 0; j < 16; j++) {
            int r = lr * 16 + j;
            sm[r][lc] = Wout[(size_t)(1024 + by * 64 + r) * H_DIM + bx * 64 + lc];
        }
        __syncthreads();
        #pragma unroll 4
        for (int j = 0; j < 16; j++) {
            int nl = lr * 16 + j;
            float v = sm[lc][nl];
            int n = bx * 64 + nl;
            int k = F_DIM + by * 64 + lc;
            g_B[(size_t)n * K_TOT + k] = __float2half(v);
        }
        return;
    }

    // ---- fold: 8 rows x 256 cols per block ----
    __shared__ float a_sh[8][H_DIM];
    int grp = b >> 1, ch = b & 1;
    int kind, row0, nrows;
    const float* B;
    if (grp < 32)       { kind = 0; row0 = grp * 8;        nrows = 256; B = Wout; }
    else if (grp < 97)  { kind = 1; row0 = (grp - 32) * 8; nrows = 513; B = Wout + 512 * H_DIM; }
    else if (grp < 106) { kind = 2; row0 = (grp - 97) * 8; nrows = 65;  B = Wout + 1536 * H_DIM; }
    else                { kind = 3; row0 = 0;              nrows = 1;   B = Wout; }

    if (kind == 0) {
        #pragma unroll
        for (int r = 0; r < 8; r++) {
            a_sh[r][t]       = Wf[(row0 + r) * H_DIM + t];
            a_sh[r][t + 256] = Wf[(row0 + r) * H_DIM + t + 256];
        }
    } else if (kind == 3) {
        a_sh[0][t] = bf[t]; a_sh[0][t + 256] = bf[t + 256];
        #pragma unroll
        for (int r = 1; r < 8; r++) { a_sh[r][t] = 0.f; a_sh[r][t + 256] = 0.f; }
    } else {
        float hi, lo;
        invdiv_k(t, hi, lo);
        #pragma unroll
        for (int r = 0; r < 8; r++) {
            float s, c;
            float pos = (float)(row0 + r < nrows ? row0 + r : 0);
            pe_sincos_hl(pos, hi, lo, &s, &c);
            a_sh[r][2 * t] = s; a_sh[r][2 * t + 1] = c;
        }
    }
    __syncthreads();

    int cc = ch * 256 + t;                 // output column (0..511)
    const float* Bc = B + cc;
    float acc[8];
    #pragma unroll
    for (int r = 0; r < 8; r++) acc[r] = 0.f;

    #pragma unroll 8
    for (int h = 0; h < H_DIM; h++) {
        float w = Bc[(size_t)h * H_DIM];
        #pragma unroll
        for (int r = 0; r < 8; r++) acc[r] = fmaf(a_sh[r][h], w, acc[r]);
    }

    if (kind == 0) {
        #pragma unroll
        for (int r = 0; r < 8; r++)
            g_B[(size_t)cc * K_TOT + row0 + r] = __float2half(acc[r]);
    } else if (kind == 1) {
        #pragma unroll
        for (int r = 0; r < 8; r++)
            if (row0 + r < 513) g_T2[(size_t)(row0 + r) * H_DIM + cc] = acc[r];
    } else if (kind == 2) {
        #pragma unroll
        for (int r = 0; r < 8; r++)
            if (row0 + r < 65) g_T4[(size_t)(row0 + r) * H_DIM + cc] = acc[r];
    } else {
        g_bconst[cc] = acc[0] + bo[cc];
    }
}

// ---------------- edges ----------------
__global__ void k_edges(const int* __restrict__ ei, int E) {
    int e = blockIdx.x * blockDim.x + threadIdx.x;
    if (e >= E) return;
    int u = ei[e], v = ei[E + e];
    atomicAdd(&g_deg[u], 1);
    atomicAdd(&g_deg[v], 1);
    atomicOr(&g_adj[u], 1ull << (v & 63));
    atomicOr(&g_adj[v], 1ull << (u & 63));
}

// ---------------- A plane: [x | PE(node idx)] -> fp16 (vectorized) ----------------
__global__ void k_aplanes(const float* __restrict__ x) {
    int i = blockIdx.x, t = threadIdx.x;
    int g = i >> 6, r = i & 63;
    float2 xv = *(const float2*)(x + (size_t)i * F_DIM + 2 * t);
    *(__half2*)(g_A + (size_t)i * K_TOT + 2 * t) = __floats2half2_rn(xv.x, xv.y);
    float4 sg = *(const float4*)(g_scg + g * H_DIM + 4 * t);
    float4 sr = *(const float4*)(g_scr + r * H_DIM + 4 * t);
    float s0 = sg.x * sr.y + sg.y * sr.x;
    float c0 = sg.y * sr.y - sg.x * sr.x;
    float s1 = sg.z * sr.w + sg.w * sr.z;
    float c1 = sg.w * sr.w - sg.z * sr.z;
    __half2 p0 = __floats2half2_rn(s0, c0);
    __half2 p1 = __floats2half2_rn(s1, c1);
    uint2 pk = make_uint2(*(uint32_t*)&p0, *(uint32_t*)&p1);
    *(uint2*)(g_A + (size_t)i * K_TOT + F_DIM + 4 * t) = pk;
}

// ---------------- HMMA GEMM + inline BFS + fused additive epilogue ----------------
// CTA tile 128x128, K-chunk 32, 8 warps (2m x 4n), warp tile 64x32.
// smem: per stage 2 planes (A, B) of 128 rows x 80B stride; 4 stages = 80KB (occ 2).
#define ROWB        80
#define PLANE_STR   (128 * ROWB)         // 10240
#define STAGE_STR   (2 * PLANE_STR)      // 20480
#define NSTAGE      4
#define GEMM_SMEM   (NSTAGE * STAGE_STR) // 81920
#define NCHUNK      24
#define MAXNNZ      40

struct EpiSmem {
    unsigned long long adj[128];
    float   bc[128];
    int     dg[128];
    int     nz[128];
    unsigned char v[128][MAXNNZ];
    unsigned char ct[128][MAXNNZ];
};

__global__ void __launch_bounds__(256, 2) k_gemm(float* __restrict__ out) {
    extern __shared__ char dsm[];
    uint32_t smem = smem_u32(dsm);

    int tid  = threadIdx.x;
    int lane = tid & 31;
    int wid  = tid >> 5;
    int wm   = wid & 1;
    int wn   = wid >> 1;
    int bn = blockIdx.x, bm = blockIdx.y;

    int lrow  = tid >> 1;
    int lhalf = tid & 1;
    const char* srcA = (const char*)(g_A + (size_t)(bm * 128 + lrow) * K_TOT) + lhalf * 32;
    const char* srcB = (const char*)(g_B + (size_t)(bn * 128 + lrow) * K_TOT) + lhalf * 32;
    uint32_t sdst = smem + (uint32_t)lrow * ROWB + (uint32_t)lhalf * 32;

    int q  = lane >> 3, rl = lane & 7;
    uint32_t aoff = (uint32_t)((wm * 64 + 8 * (q & 1) + rl) * ROWB + (8 * (q >> 1)) * 2);
    uint32_t boff = (uint32_t)((wn * 32 + 8 * (q >> 1) + rl) * ROWB + (8 * (q & 1)) * 2);

    float acc[4][4][4];
    #pragma unroll
    for (int a = 0; a < 4; a++)
        #pragma unroll
        for (int b = 0; b < 4; b++)
            #pragma unroll
            for (int e = 0; e < 4; e++) acc[a][b][e] = 0.f;

    // prologue: chunks 0,1,2 into stages 0,1,2
    #pragma unroll
    for (int s = 0; s < 3; s++) {
        uint32_t d = sdst + (uint32_t)s * STAGE_STR;
        cpasync16(d + 0 * PLANE_STR, srcA + s * 64);  cpasync16(d + 0 * PLANE_STR + 16, srcA + s * 64 + 16);
        cpasync16(d + 1 * PLANE_STR, srcB + s * 64);  cpasync16(d + 1 * PLANE_STR + 16, srcB + s * 64 + 16);
        CP_COMMIT();
    }

    for (int c = 0; c < NCHUNK; c++) {
        CP_WAIT2();
        __syncthreads();
        if (c + 3 < NCHUNK) {
            uint32_t d = sdst + (uint32_t)((c + 3) & 3) * STAGE_STR;
            const char* oA = srcA + (c + 3) * 64;
            const char* oB = srcB + (c + 3) * 64;
            cpasync16(d + 0 * PLANE_STR, oA);  cpasync16(d + 0 * PLANE_STR + 16, oA + 16);
            cpasync16(d + 1 * PLANE_STR, oB);  cpasync16(d + 1 * PLANE_STR + 16, oB + 16);
        }
        CP_COMMIT();

        uint32_t sA = smem + (uint32_t)(c & 3) * STAGE_STR;
        uint32_t sB = sA + PLANE_STR;

        #pragma unroll
        for (int kk = 0; kk < 2; kk++) {
            uint32_t ah[4][4];
            #pragma unroll
            for (int mf = 0; mf < 4; mf++) {
                uint32_t ad = sA + aoff + (uint32_t)mf * (16 * ROWB) + (uint32_t)kk * 32;
                LDSM4(ah[mf], ad);
            }
            uint32_t bh[2][4];
            #pragma unroll
            for (int nf2 = 0; nf2 < 2; nf2++) {
                uint32_t bd = sB + boff + (uint32_t)nf2 * (16 * ROWB) + (uint32_t)kk * 32;
                LDSM4(bh[nf2], bd);
            }
            #pragma unroll
            for (int mf = 0; mf < 4; mf++) {
                #pragma unroll
                for (int nf = 0; nf < 4; nf++) {
                    int nf2 = nf >> 1, nh = nf & 1;
                    MMA16816(acc[mf][nf], ah[mf], &bh[nf2][nh * 2]);
                }
            }
        }
    }

    // ---- inline BFS + fused additive epilogue ----
    __syncthreads();   // mainloop smem reads done; reuse dsm
    EpiSmem* es = (EpiSmem*)dsm;
    if (tid < 128) {
        int i = bm * 128 + tid;
        es->adj[tid] = g_adj[i];
        int d = g_deg[i]; if (d > MAXDEG) d = MAXDEG;
        es->dg[tid] = d;
    } else if (tid < 256) {
        int t = tid - 128;
        es->bc[t] = g_bconst[bn * 128 + t];
    }
    __syncthreads();

    if (tid < 128) {
        int base = tid & 64;            // graph-local adjacency block
        int s = tid & 63;
        unsigned long long reach = 1ull << s;
        unsigned long long frontier = reach;
        int m = 0;
        es->v[tid][0] = 0; es->ct[tid][0] = 1; m = 1;
        int maxfin = 0;
        for (int k = 1; k < NPG; k++) {
            unsigned long long nr = 0, f = frontier;
            while (f) {
                int j = __ffsll((long long)f) - 1;
                f &= f - 1;
                nr |= es->adj[base + j];
            }
            unsigned long long nxt = nr & ~reach;
            if (!nxt) break;
            es->v[tid][m] = (unsigned char)k;
            es->ct[tid][m] = (unsigned char)__popcll(nxt);
            m++;
            maxfin = k;
            reach |= nxt;
            frontier = nxt;
        }
        int rem = NPG - __popcll(reach);
        if (rem > 0 && m < MAXNNZ) {
            es->v[tid][m] = (unsigned char)(maxfin + 1);
            es->ct[tid][m] = (unsigned char)rem;
            m++;
        }
        es->nz[tid] = m;
    }
    __syncthreads();

    int r0l = wm * 64 + (lane >> 2);
    int c0l = wn * 32 + 2 * (lane & 3);
    #pragma unroll
    for (int mf = 0; mf < 4; mf++) {
        #pragma unroll
        for (int hh = 0; hh < 2; hh++) {
            int lr = r0l + mf * 16 + hh * 8;
            int d = es->dg[lr], m = es->nz[lr];
            const float* T2r = g_T2 + (size_t)d * H_DIM + bn * 128;
            size_t orow = (size_t)(bm * 128 + lr) * H_DIM + bn * 128;
            #pragma unroll
            for (int nf = 0; nf < 4; nf++) {
                int cl = c0l + nf * 8;
                float ax = T2r[cl]     + es->bc[cl];
                float ay = T2r[cl + 1] + es->bc[cl + 1];
                for (int j = 0; j < m; j++) {
                    float w = (float)es->ct[lr][j] * (1.0f / 64.0f);
                    const float* t4 = g_T4 + (size_t)es->v[lr][j] * H_DIM + bn * 128 + cl;
                    ax = fmaf(w, t4[0], ax);
                    ay = fmaf(w, t4[1], ay);
                }
                float2 o;
                o.x = acc[mf][nf][hh * 2 + 0] + ax;
                o.y = acc[mf][nf][hh * 2 + 1] + ay;
                *(float2*)&out[orow + cl] = o;
            }
        }
    }
}

// ---------------- launch: prep0 -> {edges | aplanes | fold} -> gemm ----------------
static cudaStream_t g_s1, g_s2;
static cudaEvent_t g_evP, g_evE, g_evA;
static int g_ready = 0;

extern "C" void kernel_launch(void* const* d_in, const int* in_sizes, int n_in,
                              void* d_out, int out_size) {
    const float* x    = (const float*)d_in[0];
    const float* Wf   = (const float*)d_in[1];
    const float* bf   = (const float*)d_in[2];
    const float* Wout = (const float*)d_in[3];
    const float* bo   = (const float*)d_in[4];
    const int*   ei   = (const int*)d_in[5];
    int E = in_sizes[5] / 2;
    float* out = (float*)d_out;

    if (!g_ready) {
        cudaStreamCreateWithFlags(&g_s1, cudaStreamNonBlocking);
        cudaStreamCreateWithFlags(&g_s2, cudaStreamNonBlocking);
        cudaEventCreateWithFlags(&g_evP, cudaEventDisableTiming);
        cudaEventCreateWithFlags(&g_evE, cudaEventDisableTiming);
        cudaEventCreateWithFlags(&g_evA, cudaEventDisableTiming);
        cudaFuncSetAttribute(k_gemm, cudaFuncAttributeMaxDynamicSharedMemorySize, GEMM_SMEM);
        g_ready = 1;
    }

    // launch 1: clear + sc tables (fast)
    k_prep0<<<384, 256>>>();
    cudaEventRecord(g_evP, 0);

    // branch: edges (needs clear)
    cudaStreamWaitEvent(g_s1, g_evP, 0);
    k_edges<<<(E + 255) / 256, 256, 0, g_s1>>>(ei, E);
    cudaEventRecord(g_evE, g_s1);

    // branch: A planes (needs sc tables)
    cudaStreamWaitEvent(g_s2, g_evP, 0);
    k_aplanes<<<N_NODES, 128, 0, g_s2>>>(x);
    cudaEventRecord(g_evA, g_s2);

    // main: fold + w3t (reads only inputs)
    k_fold<<<278, 256>>>(Wf, Wout, bf, bo);

    // join + GEMM
    cudaStreamWaitEvent(0, g_evE, 0);
    cudaStreamWaitEvent(0, g_evA, 0);
    k_gemm<<<dim3(4, 128), 256, GEMM_SMEM>>>(out);
}

// round 13
// speedup vs baseline: 1.1804x; 1.1065x over previous
#include <cuda_runtime.h>
#include <cuda_fp16.h>
#include <math.h>
#include <stdint.h>

#define N_NODES 16384
#define F_DIM   256
#define H_DIM   512
#define K_TOT   768          // 256 (x) + 512 (pe)
#define NPG     64
#define NGRAPH  256
#define MAXDEG  512

// ---------------- static device scratch ----------------
__device__ __align__(16) __half g_A[N_NODES * K_TOT];   // [x | PE] fp16
__device__ __align__(16) __half g_B[H_DIM * K_TOT];     // B^T: [n][k] fp16
__device__ float g_T2[(MAXDEG + 1) * H_DIM];
__device__ float g_T4[(NPG + 1) * H_DIM];
__device__ float g_bconst[H_DIM];
__device__ unsigned long long g_adj[N_NODES];
__device__ int g_deg[N_NODES];
__device__ __align__(16) float g_scg[NGRAPH * H_DIM];   // sin/cos(64g * inv_k) pairs
__device__ __align__(16) float g_scr[NPG * H_DIM];      // sin/cos(r * inv_k) pairs

// ---------------- helpers ----------------
__device__ __forceinline__ uint32_t smem_u32(const void* p) {
    uint32_t a;
    asm("{ .reg .u64 t; cvta.to.shared.u64 t, %1; cvt.u32.u64 %0, t; }" : "=r"(a) : "l"(p));
    return a;
}
__device__ __forceinline__ void cpasync16(uint32_t dst, const void* src) {
    asm volatile("cp.async.cg.shared.global [%0], [%1], 16;" :: "r"(dst), "l"(src) : "memory");
}
#define CP_COMMIT() asm volatile("cp.async.commit_group;" ::: "memory")
#define CP_WAIT2()  asm volatile("cp.async.wait_group 2;" ::: "memory")

#define LDSM4(r, addr) \
    asm volatile("ldmatrix.sync.aligned.m8n8.x4.shared.b16 {%0,%1,%2,%3}, [%4];" \
        : "=r"((r)[0]), "=r"((r)[1]), "=r"((r)[2]), "=r"((r)[3]) : "r"(addr))

#define MMA16816(d, a, b) \
    asm volatile("mma.sync.aligned.m16n8k16.row.col.f32.f16.f16.f32 " \
        "{%0,%1,%2,%3}, {%4,%5,%6,%7}, {%8,%9}, {%0,%1,%2,%3};" \
        : "+f"((d)[0]), "+f"((d)[1]), "+f"((d)[2]), "+f"((d)[3]) \
        : "r"((a)[0]), "r"((a)[1]), "r"((a)[2]), "r"((a)[3]), "r"((b)[0]), "r"((b)[1]))

// ---------------- accurate PE angle (invdiv computed inline per thread) ----------------
__device__ __forceinline__ void invdiv_k(int k, float& hi, float& lo) {
    double v = exp(-(double)k * (9.210340371976184 / 256.0));
    hi = (float)v;
    lo = (float)(v - (double)hi);
}

__device__ __forceinline__ void pe_sincos_hl(float pos, float hi, float lo, float* s, float* c) {
    float p  = pos * hi;
    float e  = fmaf(pos, hi, -p);
    float al = fmaf(pos, lo, e);
    const float I2PI = 0.15915494309189535f;
    const float P2H  = 6.28318548202514648f;
    const float P2L  = -1.7484855e-7f;
    float q = rintf(p * I2PI);
    float r = fmaf(-q, P2H, p);
    r = fmaf(-q, P2L, r);
    r += al;
    sincosf(r, s, c);
}

// ---------------- prep0: clear deg/adj + sc tables ----------------
// blocks: [0,64) clear, [64,384) sc
__global__ void k_prep0() {
    int b = blockIdx.x, t = threadIdx.x;
    if (b < 64) {
        int i = b * 256 + t;
        g_deg[i] = 0;
        g_adj[i] = 0ull;
        return;
    }
    int bb = b - 64;
    float hi, lo;
    invdiv_k(t, hi, lo);
    float s, c;
    if (bb < NGRAPH) {
        pe_sincos_hl((float)(64 * bb), hi, lo, &s, &c);
        g_scg[bb * H_DIM + 2 * t] = s; g_scg[bb * H_DIM + 2 * t + 1] = c;
    } else {
        int r = bb - NGRAPH;
        pe_sincos_hl((float)r, hi, lo, &s, &c);
        g_scr[r * H_DIM + 2 * t] = s; g_scr[r * H_DIM + 2 * t + 1] = c;
    }
}

// ---------------- fold (R9-proven 2-row version) + w3t ----------------
// blocks: [0,128) Wc (256 rows), [128,385) T2 (514, last dummy),
//         [385,418) T4 (66, last dummy), 418 bconst, [419,483) w3t
__global__ void k_fold(const float* __restrict__ Wf, const float* __restrict__ Wout,
                       const float* __restrict__ bf, const float* __restrict__ bo) {
    int b = blockIdx.x, t = threadIdx.x;

    if (b >= 419) {             // ---- w3t ----
        __shared__ float sm[64][65];
        int idx = b - 419;
        int bx = idx & 7, by = idx >> 3;
        int lr = t >> 6, lc = t & 63;
        #pragma unroll 4
        for (int j = 0; j < 16; j++) {
            int r = lr * 16 + j;
            sm[r][lc] = Wout[(size_t)(1024 + by * 64 + r) * H_DIM + bx * 64 + lc];
        }
        __syncthreads();
        #pragma unroll 4
        for (int j = 0; j < 16; j++) {
            int nl = lr * 16 + j;
            float v = sm[lc][nl];
            int n = bx * 64 + nl;
            int k = F_DIM + by * 64 + lc;
            g_B[(size_t)n * K_TOT + k] = __float2half(v);
        }
        return;
    }

    // ---- fold: 2 rows per block ----
    __shared__ float a_sh[2][H_DIM];
    int kind, row0;
    const float* B;
    if (b < 128)      { kind = 0; row0 = b * 2;         B = Wout; }
    else if (b < 385) { kind = 1; row0 = (b - 128) * 2; B = Wout + 512 * H_DIM; }
    else if (b < 418) { kind = 2; row0 = (b - 385) * 2; B = Wout + 1536 * H_DIM; }
    else              { kind = 3; row0 = 0;             B = Wout; }

    if (kind == 0) {
        a_sh[0][t] = Wf[row0 * H_DIM + t];       a_sh[0][t + 256] = Wf[row0 * H_DIM + t + 256];
        a_sh[1][t] = Wf[(row0 + 1) * H_DIM + t]; a_sh[1][t + 256] = Wf[(row0 + 1) * H_DIM + t + 256];
    } else if (kind == 3) {
        a_sh[0][t] = bf[t]; a_sh[0][t + 256] = bf[t + 256];
        a_sh[1][t] = 0.f;   a_sh[1][t + 256] = 0.f;
    } else {
        float hi, lo;
        invdiv_k(t, hi, lo);
        #pragma unroll
        for (int rr = 0; rr < 2; rr++) {
            float s, c;
            pe_sincos_hl((float)(row0 + rr), hi, lo, &s, &c);
            a_sh[rr][2 * t] = s; a_sh[rr][2 * t + 1] = c;
        }
    }
    __syncthreads();

    float acc00 = 0.f, acc01 = 0.f, acc10 = 0.f, acc11 = 0.f;
    const float2* Bp = ((const float2*)B) + t;
    #pragma unroll 4
    for (int h = 0; h < H_DIM; h++) {
        float2 w = Bp[(size_t)h * 256];
        float a0 = a_sh[0][h], a1 = a_sh[1][h];
        acc00 = fmaf(a0, w.x, acc00); acc01 = fmaf(a0, w.y, acc01);
        acc10 = fmaf(a1, w.x, acc10); acc11 = fmaf(a1, w.y, acc11);
    }

    int c0 = 2 * t;
    if (kind == 0) {
        g_B[(size_t)c0 * K_TOT + row0]           = __float2half(acc00);
        g_B[(size_t)(c0 + 1) * K_TOT + row0]     = __float2half(acc01);
        g_B[(size_t)c0 * K_TOT + row0 + 1]       = __float2half(acc10);
        g_B[(size_t)(c0 + 1) * K_TOT + row0 + 1] = __float2half(acc11);
    } else if (kind == 1) {
        if (row0 <= MAXDEG)     { g_T2[(size_t)row0 * H_DIM + c0] = acc00; g_T2[(size_t)row0 * H_DIM + c0 + 1] = acc01; }
        if (row0 + 1 <= MAXDEG) { g_T2[(size_t)(row0 + 1) * H_DIM + c0] = acc10; g_T2[(size_t)(row0 + 1) * H_DIM + c0 + 1] = acc11; }
    } else if (kind == 2) {
        if (row0 <= NPG)     { g_T4[(size_t)row0 * H_DIM + c0] = acc00; g_T4[(size_t)row0 * H_DIM + c0 + 1] = acc01; }
        if (row0 + 1 <= NPG) { g_T4[(size_t)(row0 + 1) * H_DIM + c0] = acc10; g_T4[(size_t)(row0 + 1) * H_DIM + c0 + 1] = acc11; }
    } else {
        g_bconst[c0]     = acc00 + bo[c0];
        g_bconst[c0 + 1] = acc01 + bo[c0 + 1];
    }
}

// ---------------- edges ----------------
__global__ void k_edges(const int* __restrict__ ei, int E) {
    int e = blockIdx.x * blockDim.x + threadIdx.x;
    if (e >= E) return;
    int u = ei[e], v = ei[E + e];
    atomicAdd(&g_deg[u], 1);
    atomicAdd(&g_deg[v], 1);
    atomicOr(&g_adj[u], 1ull << (v & 63));
    atomicOr(&g_adj[v], 1ull << (u & 63));
}

// ---------------- A plane: [x | PE(node idx)] -> fp16 (vectorized) ----------------
__global__ void k_aplanes(const float* __restrict__ x) {
    int i = blockIdx.x, t = threadIdx.x;
    int g = i >> 6, r = i & 63;
    float2 xv = *(const float2*)(x + (size_t)i * F_DIM + 2 * t);
    *(__half2*)(g_A + (size_t)i * K_TOT + 2 * t) = __floats2half2_rn(xv.x, xv.y);
    float4 sg = *(const float4*)(g_scg + g * H_DIM + 4 * t);
    float4 sr = *(const float4*)(g_scr + r * H_DIM + 4 * t);
    float s0 = sg.x * sr.y + sg.y * sr.x;
    float c0 = sg.y * sr.y - sg.x * sr.x;
    float s1 = sg.z * sr.w + sg.w * sr.z;
    float c1 = sg.w * sr.w - sg.z * sr.z;
    __half2 p0 = __floats2half2_rn(s0, c0);
    __half2 p1 = __floats2half2_rn(s1, c1);
    uint2 pk = make_uint2(*(uint32_t*)&p0, *(uint32_t*)&p1);
    *(uint2*)(g_A + (size_t)i * K_TOT + F_DIM + 4 * t) = pk;
}

// ---------------- HMMA GEMM + inline BFS + fused additive epilogue ----------------
// CTA tile 128x128, K-chunk 32, 8 warps (2m x 4n), warp tile 64x32.
// smem: per stage 2 planes (A, B) of 128 rows x 80B stride; 4 stages = 80KB (occ 2).
#define ROWB        80
#define PLANE_STR   (128 * ROWB)         // 10240
#define STAGE_STR   (2 * PLANE_STR)      // 20480
#define NSTAGE      4
#define GEMM_SMEM   (NSTAGE * STAGE_STR) // 81920
#define NCHUNK      24
#define MAXNNZ      40

struct EpiSmem {
    unsigned long long adj[128];
    float   bc[128];
    int     dg[128];
    int     nz[128];
    unsigned char v[128][MAXNNZ];
    unsigned char ct[128][MAXNNZ];
};

__global__ void __launch_bounds__(256, 2) k_gemm(float* __restrict__ out) {
    extern __shared__ char dsm[];
    uint32_t smem = smem_u32(dsm);

    int tid  = threadIdx.x;
    int lane = tid & 31;
    int wid  = tid >> 5;
    int wm   = wid & 1;
    int wn   = wid >> 1;
    int bn = blockIdx.x, bm = blockIdx.y;

    int lrow  = tid >> 1;
    int lhalf = tid & 1;
    const char* srcA = (const char*)(g_A + (size_t)(bm * 128 + lrow) * K_TOT) + lhalf * 32;
    const char* srcB = (const char*)(g_B + (size_t)(bn * 128 + lrow) * K_TOT) + lhalf * 32;
    uint32_t sdst = smem + (uint32_t)lrow * ROWB + (uint32_t)lhalf * 32;

    int q  = lane >> 3, rl = lane & 7;
    uint32_t aoff = (uint32_t)((wm * 64 + 8 * (q & 1) + rl) * ROWB + (8 * (q >> 1)) * 2);
    uint32_t boff = (uint32_t)((wn * 32 + 8 * (q >> 1) + rl) * ROWB + (8 * (q & 1)) * 2);

    float acc[4][4][4];
    #pragma unroll
    for (int a = 0; a < 4; a++)
        #pragma unroll
        for (int b = 0; b < 4; b++)
            #pragma unroll
            for (int e = 0; e < 4; e++) acc[a][b][e] = 0.f;

    // prologue: chunks 0,1,2 into stages 0,1,2
    #pragma unroll
    for (int s = 0; s < 3; s++) {
        uint32_t d = sdst + (uint32_t)s * STAGE_STR;
        cpasync16(d + 0 * PLANE_STR, srcA + s * 64);  cpasync16(d + 0 * PLANE_STR + 16, srcA + s * 64 + 16);
        cpasync16(d + 1 * PLANE_STR, srcB + s * 64);  cpasync16(d + 1 * PLANE_STR + 16, srcB + s * 64 + 16);
        CP_COMMIT();
    }

    for (int c = 0; c < NCHUNK; c++) {
        CP_WAIT2();
        __syncthreads();
        if (c + 3 < NCHUNK) {
            uint32_t d = sdst + (uint32_t)((c + 3) & 3) * STAGE_STR;
            const char* oA = srcA + (c + 3) * 64;
            const char* oB = srcB + (c + 3) * 64;
            cpasync16(d + 0 * PLANE_STR, oA);  cpasync16(d + 0 * PLANE_STR + 16, oA + 16);
            cpasync16(d + 1 * PLANE_STR, oB);  cpasync16(d + 1 * PLANE_STR + 16, oB + 16);
        }
        CP_COMMIT();

        uint32_t sA = smem + (uint32_t)(c & 3) * STAGE_STR;
        uint32_t sB = sA + PLANE_STR;

        #pragma unroll
        for (int kk = 0; kk < 2; kk++) {
            uint32_t ah[4][4];
            #pragma unroll
            for (int mf = 0; mf < 4; mf++) {
                uint32_t ad = sA + aoff + (uint32_t)mf * (16 * ROWB) + (uint32_t)kk * 32;
                LDSM4(ah[mf], ad);
            }
            uint32_t bh[2][4];
            #pragma unroll
            for (int nf2 = 0; nf2 < 2; nf2++) {
                uint32_t bd = sB + boff + (uint32_t)nf2 * (16 * ROWB) + (uint32_t)kk * 32;
                LDSM4(bh[nf2], bd);
            }
            #pragma unroll
            for (int mf = 0; mf < 4; mf++) {
                #pragma unroll
                for (int nf = 0; nf < 4; nf++) {
                    int nf2 = nf >> 1, nh = nf & 1;
                    MMA16816(acc[mf][nf], ah[mf], &bh[nf2][nh * 2]);
                }
            }
        }
    }

    // ---- inline BFS + fused additive epilogue ----
    __syncthreads();   // mainloop smem reads done; reuse dsm
    EpiSmem* es = (EpiSmem*)dsm;
    if (tid < 128) {
        int i = bm * 128 + tid;
        es->adj[tid] = g_adj[i];
        int d = g_deg[i]; if (d > MAXDEG) d = MAXDEG;
        es->dg[tid] = d;
    } else if (tid < 256) {
        int t = tid - 128;
        es->bc[t] = g_bconst[bn * 128 + t];
    }
    __syncthreads();

    if (tid < 128) {
        int base = tid & 64;            // graph-local adjacency block
        int s = tid & 63;
        unsigned long long reach = 1ull << s;
        unsigned long long frontier = reach;
        int m = 0;
        es->v[tid][0] = 0; es->ct[tid][0] = 1; m = 1;
        int maxfin = 0;
        for (int k = 1; k < NPG; k++) {
            unsigned long long nr = 0, f = frontier;
            while (f) {
                int j = __ffsll((long long)f) - 1;
                f &= f - 1;
                nr |= es->adj[base + j];
            }
            unsigned long long nxt = nr & ~reach;
            if (!nxt) break;
            es->v[tid][m] = (unsigned char)k;
            es->ct[tid][m] = (unsigned char)__popcll(nxt);
            m++;
            maxfin = k;
            reach |= nxt;
            frontier = nxt;
        }
        int rem = NPG - __popcll(reach);
        if (rem > 0 && m < MAXNNZ) {
            es->v[tid][m] = (unsigned char)(maxfin + 1);
            es->ct[tid][m] = (unsigned char)rem;
            m++;
        }
        es->nz[tid] = m;
    }
    __syncthreads();

    int r0l = wm * 64 + (lane >> 2);
    int c0l = wn * 32 + 2 * (lane & 3);
    #pragma unroll
    for (int mf = 0; mf < 4; mf++) {
        #pragma unroll
        for (int hh = 0; hh < 2; hh++) {
            int lr = r0l + mf * 16 + hh * 8;
            int d = es->dg[lr], m = es->nz[lr];
            const float* T2r = g_T2 + (size_t)d * H_DIM + bn * 128;
            size_t orow = (size_t)(bm * 128 + lr) * H_DIM + bn * 128;
            #pragma unroll
            for (int nf = 0; nf < 4; nf++) {
                int cl = c0l + nf * 8;
                float ax = T2r[cl]     + es->bc[cl];
                float ay = T2r[cl + 1] + es->bc[cl + 1];
                for (int j = 0; j < m; j++) {
                    float w = (float)es->ct[lr][j] * (1.0f / 64.0f);
                    const float* t4 = g_T4 + (size_t)es->v[lr][j] * H_DIM + bn * 128 + cl;
                    ax = fmaf(w, t4[0], ax);
                    ay = fmaf(w, t4[1], ay);
                }
                float2 o;
                o.x = acc[mf][nf][hh * 2 + 0] + ax;
                o.y = acc[mf][nf][hh * 2 + 1] + ay;
                *(float2*)&out[orow + cl] = o;
            }
        }
    }
}

// ---------------- launch: legal capture fork ----------------
// evRoot on stream0 -> s1: prep0 -> edges ; s2: (after prep0) aplanes
// stream0: fold immediately ; join evE+evA -> gemm
static cudaStream_t g_s1, g_s2;
static cudaEvent_t g_evRoot, g_evP, g_evE, g_evA;
static int g_ready = 0;

extern "C" void kernel_launch(void* const* d_in, const int* in_sizes, int n_in,
                              void* d_out, int out_size) {
    const float* x    = (const float*)d_in[0];
    const float* Wf   = (const float*)d_in[1];
    const float* bf   = (const float*)d_in[2];
    const float* Wout = (const float*)d_in[3];
    const float* bo   = (const float*)d_in[4];
    const int*   ei   = (const int*)d_in[5];
    int E = in_sizes[5] / 2;
    float* out = (float*)d_out;

    if (!g_ready) {
        cudaStreamCreateWithFlags(&g_s1, cudaStreamNonBlocking);
        cudaStreamCreateWithFlags(&g_s2, cudaStreamNonBlocking);
        cudaEventCreateWithFlags(&g_evRoot, cudaEventDisableTiming);
        cudaEventCreateWithFlags(&g_evP, cudaEventDisableTiming);
        cudaEventCreateWithFlags(&g_evE, cudaEventDisableTiming);
        cudaEventCreateWithFlags(&g_evA, cudaEventDisableTiming);
        cudaFuncSetAttribute(k_gemm, cudaFuncAttributeMaxDynamicSharedMemorySize, GEMM_SMEM);
        g_ready = 1;
    }

    // fork point recorded on the capture-origin stream
    cudaEventRecord(g_evRoot, 0);

    // s1: prep0 -> edges
    cudaStreamWaitEvent(g_s1, g_evRoot, 0);
    k_prep0<<<384, 256, 0, g_s1>>>();
    cudaEventRecord(g_evP, g_s1);
    k_edges<<<(E + 255) / 256, 256, 0, g_s1>>>(ei, E);
    cudaEventRecord(g_evE, g_s1);

    // s2: aplanes (needs sc tables from prep0)
    cudaStreamWaitEvent(g_s2, g_evP, 0);
    k_aplanes<<<N_NODES, 128, 0, g_s2>>>(x);
    cudaEventRecord(g_evA, g_s2);

    // origin stream: fold starts immediately (reads only inputs)
    k_fold<<<483, 256>>>(Wf, Wout, bf, bo);

    // join + GEMM
    cudaStreamWaitEvent(0, g_evE, 0);
    cudaStreamWaitEvent(0, g_evA, 0);
    k_gemm<<<dim3(4, 128), 256, GEMM_SMEM>>>(out);
}

// round 14
// speedup vs baseline: 1.1871x; 1.0057x over previous
#include <cuda_runtime.h>
#include <cuda_fp16.h>
#include <math.h>
#include <stdint.h>

#define N_NODES 16384
#define F_DIM   256
#define H_DIM   512
#define K_TOT   768          // 256 (x) + 512 (pe)
#define NPG     64
#define NGRAPH  256
#define MAXDEG  512

// ---------------- static device scratch ----------------
__device__ __align__(16) __half g_A[N_NODES * K_TOT];   // [x | PE] fp16
__device__ __align__(16) __half g_B[H_DIM * K_TOT];     // B^T: [n][k] fp16
__device__ float g_T2[(MAXDEG + 1) * H_DIM];
__device__ float g_T4[(NPG + 1) * H_DIM];
__device__ float g_bconst[H_DIM];
__device__ unsigned long long g_adj[N_NODES];
__device__ int g_deg[N_NODES];
__device__ __align__(16) float g_scg[NGRAPH * H_DIM];   // sin/cos(64g * inv_k)
__device__ __align__(16) float g_scr[NPG * H_DIM];      // sin/cos(r * inv_k)
__device__ __align__(16) float g_peb[576 * H_DIM];      // PE(0..575) rows (only 0..512 used)

// ---------------- helpers ----------------
__device__ __forceinline__ uint32_t smem_u32(const void* p) {
    uint32_t a;
    asm("{ .reg .u64 t; cvta.to.shared.u64 t, %1; cvt.u32.u64 %0, t; }" : "=r"(a) : "l"(p));
    return a;
}
__device__ __forceinline__ void cpasync16(uint32_t dst, const void* src) {
    asm volatile("cp.async.cg.shared.global [%0], [%1], 16;" :: "r"(dst), "l"(src) : "memory");
}
#define CP_COMMIT() asm volatile("cp.async.commit_group;" ::: "memory")
#define CP_WAIT2()  asm volatile("cp.async.wait_group 2;" ::: "memory")

#define LDSM4(r, addr) \
    asm volatile("ldmatrix.sync.aligned.m8n8.x4.shared.b16 {%0,%1,%2,%3}, [%4];" \
        : "=r"((r)[0]), "=r"((r)[1]), "=r"((r)[2]), "=r"((r)[3]) : "r"(addr))

#define MMA16816(d, a, b) \
    asm volatile("mma.sync.aligned.m16n8k16.row.col.f32.f16.f16.f32 " \
        "{%0,%1,%2,%3}, {%4,%5,%6,%7}, {%8,%9}, {%0,%1,%2,%3};" \
        : "+f"((d)[0]), "+f"((d)[1]), "+f"((d)[2]), "+f"((d)[3]) \
        : "r"((a)[0]), "r"((a)[1]), "r"((a)[2]), "r"((a)[3]), "r"((b)[0]), "r"((b)[1]))

// ---------------- accurate PE angle ----------------
__device__ __forceinline__ void invdiv_k(int k, float& hi, float& lo) {
    double v = exp(-(double)k * (9.210340371976184 / 256.0));
    hi = (float)v;
    lo = (float)(v - (double)hi);
}

__device__ __forceinline__ void pe_sincos_hl(float pos, float hi, float lo, float* s, float* c) {
    float p  = pos * hi;
    float e  = fmaf(pos, hi, -p);
    float al = fmaf(pos, lo, e);
    const float I2PI = 0.15915494309189535f;
    const float P2H  = 6.28318548202514648f;
    const float P2L  = -1.7484855e-7f;
    float q = rintf(p * I2PI);
    float r = fmaf(-q, P2H, p);
    r = fmaf(-q, P2L, r);
    r += al;
    sincosf(r, s, c);
}

// ---------------- prep0: clear | sc tables | PE row buffer ----------------
// blocks: [0,64) clear, [64,384) sc, [384,672) PEbuf (2 rows each)
__global__ void k_prep0() {
    int b = blockIdx.x, t = threadIdx.x;
    if (b < 64) {
        int i = b * 256 + t;
        g_deg[i] = 0;
        g_adj[i] = 0ull;
        return;
    }
    float hi, lo;
    invdiv_k(t, hi, lo);
    if (b < 384) {
        int bb = b - 64;
        float s, c;
        if (bb < NGRAPH) {
            pe_sincos_hl((float)(64 * bb), hi, lo, &s, &c);
            g_scg[bb * H_DIM + 2 * t] = s; g_scg[bb * H_DIM + 2 * t + 1] = c;
        } else {
            int r = bb - NGRAPH;
            pe_sincos_hl((float)r, hi, lo, &s, &c);
            g_scr[r * H_DIM + 2 * t] = s; g_scr[r * H_DIM + 2 * t + 1] = c;
        }
        return;
    }
    int bb = b - 384;          // PEbuf rows 2bb, 2bb+1
    #pragma unroll
    for (int rr = 0; rr < 2; rr++) {
        int row = 2 * bb + rr;
        float s, c;
        pe_sincos_hl((float)row, hi, lo, &s, &c);
        g_peb[(size_t)row * H_DIM + 2 * t] = s;
        g_peb[(size_t)row * H_DIM + 2 * t + 1] = c;
    }
}

// ---------------- fold v4: tiled GEMMs (BM=64, BN=32, BK=32) ----------------
// blocks: [0,64)  seg0 Wc   (4 mtiles x 16 ntiles), A=Wf,   W=W1,  out=g_B (transposed, half)
//         [64,208) seg1 T2  (9 x 16),               A=PEbuf, W=W2, out=g_T2 (rows<513)
//         [208,240) seg2 T4 (2 x 16),               A=PEbuf, W=W4, out=g_T4 (rows<65)
//         240      bconst
//         [241,305) w3t
__global__ void k_fold(const float* __restrict__ Wf, const float* __restrict__ Wout,
                       const float* __restrict__ bf, const float* __restrict__ bo) {
    __shared__ float sbuf[64 * 65];      // shared scratch for all roles (16.6KB)
    int b = blockIdx.x, t = threadIdx.x;

    if (b >= 241) {             // ---- w3t ----
        float (*sm)[65] = (float(*)[65])sbuf;
        int idx = b - 241;
        int bx = idx & 7, by = idx >> 3;
        int lr = t >> 6, lc = t & 63;
        #pragma unroll 4
        for (int j = 0; j < 16; j++) {
            int r = lr * 16 + j;
            sm[r][lc] = Wout[(size_t)(1024 + by * 64 + r) * H_DIM + bx * 64 + lc];
        }
        __syncthreads();
        #pragma unroll 4
        for (int j = 0; j < 16; j++) {
            int nl = lr * 16 + j;
            float v = sm[lc][nl];
            int n = bx * 64 + nl;
            int k = F_DIM + by * 64 + lc;
            g_B[(size_t)n * K_TOT + k] = __float2half(v);
        }
        return;
    }

    if (b == 240) {             // ---- bconst ----
        float* ash = sbuf;
        ash[t] = bf[t]; ash[t + 256] = bf[t + 256];
        __syncthreads();
        float acc0 = 0.f, acc1 = 0.f;
        const float2* Bp = ((const float2*)Wout) + t;
        #pragma unroll 4
        for (int h = 0; h < H_DIM; h++) {
            float2 w = Bp[(size_t)h * 256];
            acc0 = fmaf(ash[h], w.x, acc0);
            acc1 = fmaf(ash[h], w.y, acc1);
        }
        g_bconst[2 * t]     = acc0 + bo[2 * t];
        g_bconst[2 * t + 1] = acc1 + bo[2 * t + 1];
        return;
    }

    // ---- tiled GEMM segments ----
    float (*As)[36] = (float(*)[36])sbuf;                 // 64 x 36 floats (9216B)
    float (*Bs)[36] = (float(*)[36])(sbuf + 64 * 36);     // 32 x 36 floats (4608B)

    int seg, mt, nt;
    if (b < 64)       { seg = 0; mt = b >> 4;          nt = b & 15; }
    else if (b < 208) { seg = 1; mt = (b - 64) >> 4;   nt = (b - 64) & 15; }
    else              { seg = 2; mt = (b - 208) >> 4;  nt = (b - 208) & 15; }

    const float* Asrc = (seg == 0) ? Wf : g_peb;
    const float* W = Wout + (seg == 0 ? 0 : (seg == 1 ? 512 * H_DIM : 1536 * H_DIM));
    int row0 = mt * 64, col0 = nt * 32;

    int tx = t & 31, ty = t >> 5;       // col = col0+tx, rows = row0 + ty*8 + j
    int ar = t >> 2, ac = (t & 3) * 8;  // A-tile load: row ar, cols ac..ac+7
    int br = t >> 3, bc = (t & 7) * 4;  // B-tile load: row br, cols bc..bc+3

    float acc[8];
    #pragma unroll
    for (int j = 0; j < 8; j++) acc[j] = 0.f;

    for (int k0 = 0; k0 < H_DIM; k0 += 32) {
        float4 a0 = *(const float4*)&Asrc[(size_t)(row0 + ar) * H_DIM + k0 + ac];
        float4 a1 = *(const float4*)&Asrc[(size_t)(row0 + ar) * H_DIM + k0 + ac + 4];
        float4 bv = *(const float4*)&W[(size_t)(k0 + br) * H_DIM + col0 + bc];
        __syncthreads();
        *(float4*)&As[ar][ac]     = a0;
        *(float4*)&As[ar][ac + 4] = a1;
        *(float4*)&Bs[br][bc]     = bv;
        __syncthreads();
        #pragma unroll
        for (int k = 0; k < 32; k++) {
            float bvk = Bs[k][tx];
            #pragma unroll
            for (int j = 0; j < 8; j++)
                acc[j] = fmaf(As[ty * 8 + j][k], bvk, acc[j]);
        }
    }

    int c = col0 + tx;
    int rbase = row0 + ty * 8;
    if (seg == 0) {
        __half hb[8];
        #pragma unroll
        for (int j = 0; j < 8; j++) hb[j] = __float2half(acc[j]);
        *(uint4*)&g_B[(size_t)c * K_TOT + rbase] = *(uint4*)hb;
    } else if (seg == 1) {
        #pragma unroll
        for (int j = 0; j < 8; j++)
            if (rbase + j < 513) g_T2[(size_t)(rbase + j) * H_DIM + c] = acc[j];
    } else {
        #pragma unroll
        for (int j = 0; j < 8; j++)
            if (rbase + j < 65) g_T4[(size_t)(rbase + j) * H_DIM + c] = acc[j];
    }
}

// ---------------- edges ----------------
__global__ void k_edges(const int* __restrict__ ei, int E) {
    int e = blockIdx.x * blockDim.x + threadIdx.x;
    if (e >= E) return;
    int u = ei[e], v = ei[E + e];
    atomicAdd(&g_deg[u], 1);
    atomicAdd(&g_deg[v], 1);
    atomicOr(&g_adj[u], 1ull << (v & 63));
    atomicOr(&g_adj[v], 1ull << (u & 63));
}

// ---------------- A plane: [x | PE(node idx)] -> fp16 (vectorized) ----------------
__global__ void k_aplanes(const float* __restrict__ x) {
    int i = blockIdx.x, t = threadIdx.x;
    int g = i >> 6, r = i & 63;
    float2 xv = *(const float2*)(x + (size_t)i * F_DIM + 2 * t);
    *(__half2*)(g_A + (size_t)i * K_TOT + 2 * t) = __floats2half2_rn(xv.x, xv.y);
    float4 sg = *(const float4*)(g_scg + g * H_DIM + 4 * t);
    float4 sr = *(const float4*)(g_scr + r * H_DIM + 4 * t);
    float s0 = sg.x * sr.y + sg.y * sr.x;
    float c0 = sg.y * sr.y - sg.x * sr.x;
    float s1 = sg.z * sr.w + sg.w * sr.z;
    float c1 = sg.w * sr.w - sg.z * sr.z;
    __half2 p0 = __floats2half2_rn(s0, c0);
    __half2 p1 = __floats2half2_rn(s1, c1);
    uint2 pk = make_uint2(*(uint32_t*)&p0, *(uint32_t*)&p1);
    *(uint2*)(g_A + (size_t)i * K_TOT + F_DIM + 4 * t) = pk;
}

// ---------------- HMMA GEMM + inline BFS + fused additive epilogue ----------------
#define ROWB        80
#define PLANE_STR   (128 * ROWB)         // 10240
#define STAGE_STR   (2 * PLANE_STR)      // 20480
#define NSTAGE      4
#define GEMM_SMEM   (NSTAGE * STAGE_STR) // 81920
#define NCHUNK      24
#define MAXNNZ      40

struct EpiSmem {
    unsigned long long adj[128];
    float   bc[128];
    int     dg[128];
    int     nz[128];
    unsigned char v[128][MAXNNZ];
    unsigned char ct[128][MAXNNZ];
};

__global__ void __launch_bounds__(256, 2) k_gemm(float* __restrict__ out) {
    extern __shared__ char dsm[];
    uint32_t smem = smem_u32(dsm);

    int tid  = threadIdx.x;
    int lane = tid & 31;
    int wid  = tid >> 5;
    int wm   = wid & 1;
    int wn   = wid >> 1;
    int bn = blockIdx.x, bm = blockIdx.y;

    int lrow  = tid >> 1;
    int lhalf = tid & 1;
    const char* srcA = (const char*)(g_A + (size_t)(bm * 128 + lrow) * K_TOT) + lhalf * 32;
    const char* srcB = (const char*)(g_B + (size_t)(bn * 128 + lrow) * K_TOT) + lhalf * 32;
    uint32_t sdst = smem + (uint32_t)lrow * ROWB + (uint32_t)lhalf * 32;

    int q  = lane >> 3, rl = lane & 7;
    uint32_t aoff = (uint32_t)((wm * 64 + 8 * (q & 1) + rl) * ROWB + (8 * (q >> 1)) * 2);
    uint32_t boff = (uint32_t)((wn * 32 + 8 * (q >> 1) + rl) * ROWB + (8 * (q & 1)) * 2);

    float acc[4][4][4];
    #pragma unroll
    for (int a = 0; a < 4; a++)
        #pragma unroll
        for (int b = 0; b < 4; b++)
            #pragma unroll
            for (int e = 0; e < 4; e++) acc[a][b][e] = 0.f;

    #pragma unroll
    for (int s = 0; s < 3; s++) {
        uint32_t d = sdst + (uint32_t)s * STAGE_STR;
        cpasync16(d + 0 * PLANE_STR, srcA + s * 64);  cpasync16(d + 0 * PLANE_STR + 16, srcA + s * 64 + 16);
        cpasync16(d + 1 * PLANE_STR, srcB + s * 64);  cpasync16(d + 1 * PLANE_STR + 16, srcB + s * 64 + 16);
        CP_COMMIT();
    }

    for (int c = 0; c < NCHUNK; c++) {
        CP_WAIT2();
        __syncthreads();
        if (c + 3 < NCHUNK) {
            uint32_t d = sdst + (uint32_t)((c + 3) & 3) * STAGE_STR;
            const char* oA = srcA + (c + 3) * 64;
            const char* oB = srcB + (c + 3) * 64;
            cpasync16(d + 0 * PLANE_STR, oA);  cpasync16(d + 0 * PLANE_STR + 16, oA + 16);
            cpasync16(d + 1 * PLANE_STR, oB);  cpasync16(d + 1 * PLANE_STR + 16, oB + 16);
        }
        CP_COMMIT();

        uint32_t sA = smem + (uint32_t)(c & 3) * STAGE_STR;
        uint32_t sB = sA + PLANE_STR;

        #pragma unroll
        for (int kk = 0; kk < 2; kk++) {
            uint32_t ah[4][4];
            #pragma unroll
            for (int mf = 0; mf < 4; mf++) {
                uint32_t ad = sA + aoff + (uint32_t)mf * (16 * ROWB) + (uint32_t)kk * 32;
                LDSM4(ah[mf], ad);
            }
            uint32_t bh[2][4];
            #pragma unroll
            for (int nf2 = 0; nf2 < 2; nf2++) {
                uint32_t bd = sB + boff + (uint32_t)nf2 * (16 * ROWB) + (uint32_t)kk * 32;
                LDSM4(bh[nf2], bd);
            }
            #pragma unroll
            for (int mf = 0; mf < 4; mf++) {
                #pragma unroll
                for (int nf = 0; nf < 4; nf++) {
                    int nf2 = nf >> 1, nh = nf & 1;
                    MMA16816(acc[mf][nf], ah[mf], &bh[nf2][nh * 2]);
                }
            }
        }
    }

    // ---- inline BFS + fused additive epilogue ----
    __syncthreads();
    EpiSmem* es = (EpiSmem*)dsm;
    if (tid < 128) {
        int i = bm * 128 + tid;
        es->adj[tid] = g_adj[i];
        int d = g_deg[i]; if (d > MAXDEG) d = MAXDEG;
        es->dg[tid] = d;
    } else if (tid < 256) {
        int t = tid - 128;
        es->bc[t] = g_bconst[bn * 128 + t];
    }
    __syncthreads();

    if (tid < 128) {
        int base = tid & 64;
        int s = tid & 63;
        unsigned long long reach = 1ull << s;
        unsigned long long frontier = reach;
        int m = 0;
        es->v[tid][0] = 0; es->ct[tid][0] = 1; m = 1;
        int maxfin = 0;
        for (int k = 1; k < NPG; k++) {
            unsigned long long nr = 0, f = frontier;
            while (f) {
                int j = __ffsll((long long)f) - 1;
                f &= f - 1;
                nr |= es->adj[base + j];
            }
            unsigned long long nxt = nr & ~reach;
            if (!nxt) break;
            es->v[tid][m] = (unsigned char)k;
            es->ct[tid][m] = (unsigned char)__popcll(nxt);
            m++;
            maxfin = k;
            reach |= nxt;
            frontier = nxt;
        }
        int rem = NPG - __popcll(reach);
        if (rem > 0 && m < MAXNNZ) {
            es->v[tid][m] = (unsigned char)(maxfin + 1);
            es->ct[tid][m] = (unsigned char)rem;
            m++;
        }
        es->nz[tid] = m;
    }
    __syncthreads();

    int r0l = wm * 64 + (lane >> 2);
    int c0l = wn * 32 + 2 * (lane & 3);
    #pragma unroll
    for (int mf = 0; mf < 4; mf++) {
        #pragma unroll
        for (int hh = 0; hh < 2; hh++) {
            int lr = r0l + mf * 16 + hh * 8;
            int d = es->dg[lr], m = es->nz[lr];
            const float* T2r = g_T2 + (size_t)d * H_DIM + bn * 128;
            size_t orow = (size_t)(bm * 128 + lr) * H_DIM + bn * 128;
            #pragma unroll
            for (int nf = 0; nf < 4; nf++) {
                int cl = c0l + nf * 8;
                float ax = T2r[cl]     + es->bc[cl];
                float ay = T2r[cl + 1] + es->bc[cl + 1];
                for (int j = 0; j < m; j++) {
                    float w = (float)es->ct[lr][j] * (1.0f / 64.0f);
                    const float* t4 = g_T4 + (size_t)es->v[lr][j] * H_DIM + bn * 128 + cl;
                    ax = fmaf(w, t4[0], ax);
                    ay = fmaf(w, t4[1], ay);
                }
                float2 o;
                o.x = acc[mf][nf][hh * 2 + 0] + ax;
                o.y = acc[mf][nf][hh * 2 + 1] + ay;
                *(float2*)&out[orow + cl] = o;
            }
        }
    }
}

// ---------------- launch ----------------
// stream0: prep0 -> fold -> (join) -> gemm
// s1 (after prep0): edges ; s2 (after prep0): aplanes
static cudaStream_t g_s1, g_s2;
static cudaEvent_t g_evP, g_evE, g_evA;
static int g_ready = 0;

extern "C" void kernel_launch(void* const* d_in, const int* in_sizes, int n_in,
                              void* d_out, int out_size) {
    const float* x    = (const float*)d_in[0];
    const float* Wf   = (const float*)d_in[1];
    const float* bf   = (const float*)d_in[2];
    const float* Wout = (const float*)d_in[3];
    const float* bo   = (const float*)d_in[4];
    const int*   ei   = (const int*)d_in[5];
    int E = in_sizes[5] / 2;
    float* out = (float*)d_out;

    if (!g_ready) {
        cudaStreamCreateWithFlags(&g_s1, cudaStreamNonBlocking);
        cudaStreamCreateWithFlags(&g_s2, cudaStreamNonBlocking);
        cudaEventCreateWithFlags(&g_evP, cudaEventDisableTiming);
        cudaEventCreateWithFlags(&g_evE, cudaEventDisableTiming);
        cudaEventCreateWithFlags(&g_evA, cudaEventDisableTiming);
        cudaFuncSetAttribute(k_gemm, cudaFuncAttributeMaxDynamicSharedMemorySize, GEMM_SMEM);
        g_ready = 1;
    }

    // stream0: prep0 (clear + sc + PEbuf)
    k_prep0<<<672, 256>>>();
    cudaEventRecord(g_evP, 0);

    // s1: edges (needs clear)
    cudaStreamWaitEvent(g_s1, g_evP, 0);
    k_edges<<<(E + 255) / 256, 256, 0, g_s1>>>(ei, E);
    cudaEventRecord(g_evE, g_s1);

    // s2: aplanes (needs sc tables)
    cudaStreamWaitEvent(g_s2, g_evP, 0);
    k_aplanes<<<N_NODES, 128, 0, g_s2>>>(x);
    cudaEventRecord(g_evA, g_s2);

    // stream0: fold (needs PEbuf)
    k_fold<<<305, 256>>>(Wf, Wout, bf, bo);

    // join + GEMM
    cudaStreamWaitEvent(0, g_evE, 0);
    cudaStreamWaitEvent(0, g_evA, 0);
    k_gemm<<<dim3(4, 128), 256, GEMM_SMEM>>>(out);
}